// round 3
// baseline (speedup 1.0000x reference)
#include <cuda_runtime.h>

// Problem constants
#define N_VOX  100000
#define CIN    64
#define COUT   64
#define NK     27
#define TILE_M 128
#define NTHREADS 128
#define LN_EPS 1e-5f

// Shared layout (48KB static):
//   As : float[64][128]  (c-major gathered features / conv-out for GEMM2)  offset 0     (8192 floats)
//   Bs : float[64][64]   (current weight tile)                             offset 8192  (4096 floats)
//   Ys : float[128][68]  (post-linear rows for layernorm; reuses As+Bs)    offset 0     (8704 floats)
#define AS_OFF 0
#define BS_OFF 8192
#define YS_STRIDE 68
#define SMEM_FLOATS 12288

__global__ __launch_bounds__(NTHREADS, 4)
void spconv_lin_ln_kernel(const float* __restrict__ feats,
                          const int*   __restrict__ nb,
                          const float* __restrict__ Wc,
                          const float* __restrict__ bc,
                          const float* __restrict__ Wl,
                          const float* __restrict__ bl,
                          const float* __restrict__ gamma,
                          const float* __restrict__ beta,
                          float* __restrict__ out)
{
    __shared__ float SM[SMEM_FLOATS];
    float* As = SM + AS_OFF;
    float* Bs = SM + BS_OFF;

    const int tid = threadIdx.x;
    const int block_row = blockIdx.x * TILE_M;
    const int i  = tid >> 3;     // 0..15 : row group (8 voxels each)
    const int j  = tid & 7;      // 0..7  : col group (8 outputs each)
    const int r0 = i * 8;
    const int c0 = j * 8;
    const int gvox = block_row + tid;   // voxel this thread gathers / normalizes
    const bool active = (gvox < N_VOX);
    const int* nrow = nb + (long)gvox * NK;

    float acc[8][8];
    #pragma unroll
    for (int a = 0; a < 8; a++)
        #pragma unroll
        for (int b = 0; b < 8; b++) acc[a][b] = 0.0f;

    // 1-deep pipelined neighbor-index prefetch: idx for tap k is loaded
    // during iteration k-1, hiding the full gmem latency.
    int idx_next = active ? nrow[0] : -1;

    // ---------------- conv over 27 offsets ----------------
    const float4* Wc4 = (const float4*)Wc;   // k*1024 float4 per tap
    for (int k = 0; k < NK; k++) {
        const int idx = idx_next;
        if (k + 1 < NK) idx_next = active ? nrow[k + 1] : -1;

        // stage W_conv[k] (64x64) into Bs, coalesced float4
        {
            const float4* W4 = Wc4 + k * (CIN * COUT / 4);
            float4* B4 = (float4*)Bs;
            #pragma unroll
            for (int t = 0; t < 8; t++) B4[tid + t * NTHREADS] = W4[tid + t * NTHREADS];
        }
        // gather one neighbor row per thread, transposed into As[c][v]
        if (idx >= 0) {
            const float4* F4 = (const float4*)(feats + (long)idx * CIN);
            #pragma unroll
            for (int c4 = 0; c4 < 16; c4++) {
                float4 f = F4[c4];
                As[(4 * c4 + 0) * TILE_M + tid] = f.x;
                As[(4 * c4 + 1) * TILE_M + tid] = f.y;
                As[(4 * c4 + 2) * TILE_M + tid] = f.z;
                As[(4 * c4 + 3) * TILE_M + tid] = f.w;
            }
        } else {
            #pragma unroll
            for (int c4 = 0; c4 < 16; c4++) {
                As[(4 * c4 + 0) * TILE_M + tid] = 0.0f;
                As[(4 * c4 + 1) * TILE_M + tid] = 0.0f;
                As[(4 * c4 + 2) * TILE_M + tid] = 0.0f;
                As[(4 * c4 + 3) * TILE_M + tid] = 0.0f;
            }
        }
        __syncthreads();

        // 8x8 register-tiled microkernel over K=64
        #pragma unroll 8
        for (int c = 0; c < CIN; c++) {
            float4 a0 = *(const float4*)(As + c * TILE_M + r0);
            float4 a1 = *(const float4*)(As + c * TILE_M + r0 + 4);
            float4 b0 = *(const float4*)(Bs + c * COUT + c0);
            float4 b1 = *(const float4*)(Bs + c * COUT + c0 + 4);
            float av[8] = {a0.x, a0.y, a0.z, a0.w, a1.x, a1.y, a1.z, a1.w};
            float bv[8] = {b0.x, b0.y, b0.z, b0.w, b1.x, b1.y, b1.z, b1.w};
            #pragma unroll
            for (int vi = 0; vi < 8; vi++)
                #pragma unroll
                for (int oi = 0; oi < 8; oi++)
                    acc[vi][oi] += av[vi] * bv[oi];
        }
        __syncthreads();
    }

    // add conv bias
    {
        float bcv[8];
        #pragma unroll
        for (int oi = 0; oi < 8; oi++) bcv[oi] = bc[c0 + oi];
        #pragma unroll
        for (int vi = 0; vi < 8; vi++)
            #pragma unroll
            for (int oi = 0; oi < 8; oi++) acc[vi][oi] += bcv[oi];
    }

    // ---------------- fused linear (second in-shared GEMM) ----------------
    // write conv result transposed into As (Xs[c][v]); stage W_lin into Bs
    #pragma unroll
    for (int oi = 0; oi < 8; oi++)
        #pragma unroll
        for (int vi = 0; vi < 8; vi++)
            As[(c0 + oi) * TILE_M + (r0 + vi)] = acc[vi][oi];
    {
        const float4* W4 = (const float4*)Wl;
        float4* B4 = (float4*)Bs;
        #pragma unroll
        for (int t = 0; t < 8; t++) B4[tid + t * NTHREADS] = W4[tid + t * NTHREADS];
    }
    __syncthreads();

    float acc2[8][8];
    #pragma unroll
    for (int a = 0; a < 8; a++)
        #pragma unroll
        for (int b = 0; b < 8; b++) acc2[a][b] = 0.0f;

    #pragma unroll 8
    for (int c = 0; c < COUT; c++) {
        float4 a0 = *(const float4*)(As + c * TILE_M + r0);
        float4 a1 = *(const float4*)(As + c * TILE_M + r0 + 4);
        float4 b0 = *(const float4*)(Bs + c * COUT + c0);
        float4 b1 = *(const float4*)(Bs + c * COUT + c0 + 4);
        float av[8] = {a0.x, a0.y, a0.z, a0.w, a1.x, a1.y, a1.z, a1.w};
        float bv[8] = {b0.x, b0.y, b0.z, b0.w, b1.x, b1.y, b1.z, b1.w};
        #pragma unroll
        for (int vi = 0; vi < 8; vi++)
            #pragma unroll
            for (int oi = 0; oi < 8; oi++)
                acc2[vi][oi] += av[vi] * bv[oi];
    }
    __syncthreads();   // done reading As/Bs; safe to overwrite with Ys

    // add linear bias, write rows for layernorm
    {
        float blv[8];
        #pragma unroll
        for (int oi = 0; oi < 8; oi++) blv[oi] = bl[c0 + oi];
        #pragma unroll
        for (int vi = 0; vi < 8; vi++)
            #pragma unroll
            for (int oi = 0; oi < 8; oi++)
                SM[(r0 + vi) * YS_STRIDE + (c0 + oi)] = acc2[vi][oi] + blv[oi];
    }
    __syncthreads();

    // ---------------- layernorm: one voxel per thread ----------------
    if (active) {
        const float* y = SM + tid * YS_STRIDE;
        float s = 0.0f;
        #pragma unroll
        for (int c4 = 0; c4 < 16; c4++) {
            float4 f = *(const float4*)(y + 4 * c4);
            s += f.x + f.y + f.z + f.w;
        }
        float mu = s * (1.0f / 64.0f);
        float v2 = 0.0f;
        #pragma unroll
        for (int c4 = 0; c4 < 16; c4++) {
            float4 f = *(const float4*)(y + 4 * c4);
            float dx = f.x - mu, dy = f.y - mu, dz = f.z - mu, dw = f.w - mu;
            v2 += dx * dx + dy * dy + dz * dz + dw * dw;
        }
        float rstd = rsqrtf(v2 * (1.0f / 64.0f) + LN_EPS);
        float4* o4 = (float4*)(out + (long)gvox * COUT);
        #pragma unroll
        for (int c4 = 0; c4 < 16; c4++) {
            float4 f = *(const float4*)(y + 4 * c4);
            float4 g = *(const float4*)(gamma + 4 * c4);
            float4 b = *(const float4*)(beta + 4 * c4);
            float4 r;
            r.x = g.x * (f.x - mu) * rstd + b.x;
            r.y = g.y * (f.y - mu) * rstd + b.y;
            r.z = g.z * (f.z - mu) * rstd + b.z;
            r.w = g.w * (f.w - mu) * rstd + b.w;
            o4[c4] = r;
        }
    }
}

extern "C" void kernel_launch(void* const* d_in, const int* in_sizes, int n_in,
                              void* d_out, int out_size)
{
    const float* feats = (const float*)d_in[0];
    const int*   nb    = (const int*)d_in[1];
    const float* Wc    = (const float*)d_in[2];
    const float* bc    = (const float*)d_in[3];
    const float* Wl    = (const float*)d_in[4];
    const float* bl    = (const float*)d_in[5];
    const float* gamma = (const float*)d_in[6];
    const float* beta  = (const float*)d_in[7];
    float* out = (float*)d_out;

    int grid = (N_VOX + TILE_M - 1) / TILE_M;   // 782
    spconv_lin_ln_kernel<<<grid, NTHREADS>>>(feats, nb, Wc, bc, Wl, bl, gamma, beta, out);
}

// round 4
// speedup vs baseline: 2.5146x; 2.5146x over previous
#include <cuda_runtime.h>

#define N_VOX    100000
#define CIN      64
#define COUT     64
#define NK       27
#define TILE_M   128
#define NTHREADS 128
#define LN_EPS   1e-5f
#define CENTER_K 13

// Dynamic shared layout (float offsets):
//   regX : 8704 floats — As(64x128, dense paths) / accS(128x68) / Ys(128x68)
//   Bs   : 4096 floats — current 64x64 weight tile
//   As2  : 1088 floats — compacted A rows (16 x stride 68)
//   list : 256 ints    — listV[128], listI[128]
//   cnt  : 1 int
#define REGX_OFF 0
#define BS_OFF   8704
#define A2_OFF   12800
#define LIST_OFF 13888
#define CNT_OFF  14144
#define SMEM_FLOATS 14160
#define SMEM_BYTES (SMEM_FLOATS * 4)

__global__ __launch_bounds__(NTHREADS, 4)
void spconv_lin_ln_kernel(const float* __restrict__ feats,
                          const int*   __restrict__ nb,
                          const float* __restrict__ Wc,
                          const float* __restrict__ bc,
                          const float* __restrict__ Wl,
                          const float* __restrict__ bl,
                          const float* __restrict__ gamma,
                          const float* __restrict__ beta,
                          float* __restrict__ out)
{
    extern __shared__ float SM[];
    float* regX = SM + REGX_OFF;          // As / accS / Ys
    float* Bs   = SM + BS_OFF;
    float* As2  = SM + A2_OFF;
    int*   listV = (int*)(SM + LIST_OFF);
    int*   listI = listV + 128;
    int*   cntP  = (int*)(SM + CNT_OFF);

    const int tid = threadIdx.x;
    const int block_row = blockIdx.x * TILE_M;
    const int gvox = block_row + tid;
    const bool active = (gvox < N_VOX);
    const int* nrow = nb + (long)gvox * NK;

    // ================= Phase 1: zero accS =================
    for (int t = tid; t < TILE_M * 68; t += NTHREADS) regX[t] = 0.0f;
    __syncthreads();

    // ================= Phase 2: off-center taps (sparse) =================
    // iterate kk=0..25 mapping to k in 0..26 skipping CENTER_K
    int idx_next = active ? nrow[0] : -1;
    for (int kk = 0; kk < 26; kk++) {
        const int k = kk + (kk >= CENTER_K ? 1 : 0);
        const int idx = idx_next;
        if (kk + 1 < 26) {
            int kn = (kk + 1) + ((kk + 1) >= CENTER_K ? 1 : 0);
            idx_next = active ? nrow[kn] : -1;
        }

        if (tid == 0) *cntP = 0;
        __syncthreads();                 // cnt zeroed; prev tap's list/As2/Bs free

        if (idx >= 0) {
            int p = atomicAdd(cntP, 1);
            listV[p] = tid;
            listI[p] = idx;
        }
        // prefetch W_k while compaction settles
        float4 w[8];
        {
            const float4* W4 = (const float4*)Wc + k * (CIN * COUT / 4);
            #pragma unroll
            for (int t = 0; t < 8; t++) w[t] = W4[tid + t * NTHREADS];
        }
        __syncthreads();
        const int cnt = *cntP;
        if (cnt == 0) continue;

        // store staged weights
        {
            float4* B4 = (float4*)Bs;
            #pragma unroll
            for (int t = 0; t < 8; t++) B4[tid + t * NTHREADS] = w[t];
        }

        for (int base = 0; base < cnt; base += 16) {
            const int rem = (cnt - base < 16) ? (cnt - base) : 16;
            // gather up to 16 rows into As2[e*68 + c] (float4 granularity)
            #pragma unroll
            for (int it = 0; it < 2; it++) {
                int s = tid + it * NTHREADS;    // slot over 16 rows x 16 float4
                int e = s >> 4, c4 = s & 15;
                if (e < rem) {
                    float4 f = *((const float4*)(feats + (long)listI[base + e] * CIN) + c4);
                    *(float4*)(As2 + e * 68 + 4 * c4) = f;
                }
            }
            __syncthreads();                 // As2 (and Bs) ready

            if (rem <= 8) {
                // 8 entries x 16 col-groups (4 outputs each)
                const int e = tid >> 4, j = tid & 15;
                const float* A = As2 + e * 68;
                float a4[4] = {0.f, 0.f, 0.f, 0.f};
                #pragma unroll
                for (int c4 = 0; c4 < 16; c4++) {
                    float4 av = *(const float4*)(A + 4 * c4);
                    float aa[4] = {av.x, av.y, av.z, av.w};
                    #pragma unroll
                    for (int u = 0; u < 4; u++) {
                        float4 b = *(const float4*)(Bs + (4 * c4 + u) * COUT + j * 4);
                        a4[0] += aa[u] * b.x;
                        a4[1] += aa[u] * b.y;
                        a4[2] += aa[u] * b.z;
                        a4[3] += aa[u] * b.w;
                    }
                }
                if (e < rem) {
                    float* P = regX + listV[base + e] * 68 + j * 4;
                    float4 o = *(float4*)P;
                    o.x += a4[0]; o.y += a4[1]; o.z += a4[2]; o.w += a4[3];
                    *(float4*)P = o;
                }
            } else {
                // 16 entries x 8 col-groups (8 outputs each)
                const int e = tid >> 3, j = tid & 7;
                const float* A = As2 + e * 68;
                float a8[8] = {0.f,0.f,0.f,0.f,0.f,0.f,0.f,0.f};
                #pragma unroll
                for (int c4 = 0; c4 < 16; c4++) {
                    float4 av = *(const float4*)(A + 4 * c4);
                    float aa[4] = {av.x, av.y, av.z, av.w};
                    #pragma unroll
                    for (int u = 0; u < 4; u++) {
                        float4 b0 = *(const float4*)(Bs + (4 * c4 + u) * COUT + j * 8);
                        float4 b1 = *(const float4*)(Bs + (4 * c4 + u) * COUT + j * 8 + 4);
                        a8[0] += aa[u] * b0.x;
                        a8[1] += aa[u] * b0.y;
                        a8[2] += aa[u] * b0.z;
                        a8[3] += aa[u] * b0.w;
                        a8[4] += aa[u] * b1.x;
                        a8[5] += aa[u] * b1.y;
                        a8[6] += aa[u] * b1.z;
                        a8[7] += aa[u] * b1.w;
                    }
                }
                if (e < rem) {
                    float* P = regX + listV[base + e] * 68 + j * 8;
                    float4 o0 = *(float4*)P;
                    float4 o1 = *(float4*)(P + 4);
                    o0.x += a8[0]; o0.y += a8[1]; o0.z += a8[2]; o0.w += a8[3];
                    o1.x += a8[4]; o1.y += a8[5]; o1.z += a8[6]; o1.w += a8[7];
                    *(float4*)P = o0;
                    *(float4*)(P + 4) = o1;
                }
            }
            __syncthreads();                 // protect As2 for next pass
        }
    }
    __syncthreads();

    // ================= Phase 3: merge accS + conv bias into registers =================
    const int i  = tid >> 3;     // row group (8 voxels)
    const int j  = tid & 7;      // col group (8 outputs)
    const int r0 = i * 8;
    const int c0 = j * 8;

    float acc[8][8];
    {
        float bcv[8];
        #pragma unroll
        for (int oi = 0; oi < 8; oi++) bcv[oi] = bc[c0 + oi];
        #pragma unroll
        for (int vi = 0; vi < 8; vi++) {
            float4 s0 = *(const float4*)(regX + (r0 + vi) * 68 + c0);
            float4 s1 = *(const float4*)(regX + (r0 + vi) * 68 + c0 + 4);
            acc[vi][0] = s0.x + bcv[0];
            acc[vi][1] = s0.y + bcv[1];
            acc[vi][2] = s0.z + bcv[2];
            acc[vi][3] = s0.w + bcv[3];
            acc[vi][4] = s1.x + bcv[4];
            acc[vi][5] = s1.y + bcv[5];
            acc[vi][6] = s1.z + bcv[6];
            acc[vi][7] = s1.w + bcv[7];
        }
    }
    __syncthreads();            // accS reads done; regX reusable as dense As

    // ================= Phase 4: center tap (dense, all rows valid) =================
    float* As = regX;           // 64 x 128
    {
        const float4* W4 = (const float4*)Wc + CENTER_K * (CIN * COUT / 4);
        float4* B4 = (float4*)Bs;
        #pragma unroll
        for (int t = 0; t < 8; t++) B4[tid + t * NTHREADS] = W4[tid + t * NTHREADS];
    }
    {
        int idx = active ? nrow[CENTER_K] : -1;
        if (idx >= 0) {
            const float4* F4 = (const float4*)(feats + (long)idx * CIN);
            #pragma unroll
            for (int c4 = 0; c4 < 16; c4++) {
                float4 f = F4[c4];
                As[(4 * c4 + 0) * TILE_M + tid] = f.x;
                As[(4 * c4 + 1) * TILE_M + tid] = f.y;
                As[(4 * c4 + 2) * TILE_M + tid] = f.z;
                As[(4 * c4 + 3) * TILE_M + tid] = f.w;
            }
        } else {
            #pragma unroll
            for (int c4 = 0; c4 < 16; c4++) {
                As[(4 * c4 + 0) * TILE_M + tid] = 0.0f;
                As[(4 * c4 + 1) * TILE_M + tid] = 0.0f;
                As[(4 * c4 + 2) * TILE_M + tid] = 0.0f;
                As[(4 * c4 + 3) * TILE_M + tid] = 0.0f;
            }
        }
    }
    __syncthreads();

    #pragma unroll 8
    for (int c = 0; c < CIN; c++) {
        float4 a0 = *(const float4*)(As + c * TILE_M + r0);
        float4 a1 = *(const float4*)(As + c * TILE_M + r0 + 4);
        float4 b0 = *(const float4*)(Bs + c * COUT + c0);
        float4 b1 = *(const float4*)(Bs + c * COUT + c0 + 4);
        float av[8] = {a0.x, a0.y, a0.z, a0.w, a1.x, a1.y, a1.z, a1.w};
        float bv[8] = {b0.x, b0.y, b0.z, b0.w, b1.x, b1.y, b1.z, b1.w};
        #pragma unroll
        for (int vi = 0; vi < 8; vi++)
            #pragma unroll
            for (int oi = 0; oi < 8; oi++)
                acc[vi][oi] += av[vi] * bv[oi];
    }
    __syncthreads();

    // ================= Phase 5: fused linear =================
    #pragma unroll
    for (int oi = 0; oi < 8; oi++)
        #pragma unroll
        for (int vi = 0; vi < 8; vi++)
            As[(c0 + oi) * TILE_M + (r0 + vi)] = acc[vi][oi];
    {
        const float4* W4 = (const float4*)Wl;
        float4* B4 = (float4*)Bs;
        #pragma unroll
        for (int t = 0; t < 8; t++) B4[tid + t * NTHREADS] = W4[tid + t * NTHREADS];
    }
    __syncthreads();

    float acc2[8][8];
    #pragma unroll
    for (int a = 0; a < 8; a++)
        #pragma unroll
        for (int b = 0; b < 8; b++) acc2[a][b] = 0.0f;

    #pragma unroll 8
    for (int c = 0; c < COUT; c++) {
        float4 a0 = *(const float4*)(As + c * TILE_M + r0);
        float4 a1 = *(const float4*)(As + c * TILE_M + r0 + 4);
        float4 b0 = *(const float4*)(Bs + c * COUT + c0);
        float4 b1 = *(const float4*)(Bs + c * COUT + c0 + 4);
        float av[8] = {a0.x, a0.y, a0.z, a0.w, a1.x, a1.y, a1.z, a1.w};
        float bv[8] = {b0.x, b0.y, b0.z, b0.w, b1.x, b1.y, b1.z, b1.w};
        #pragma unroll
        for (int vi = 0; vi < 8; vi++)
            #pragma unroll
            for (int oi = 0; oi < 8; oi++)
                acc2[vi][oi] += av[vi] * bv[oi];
    }
    __syncthreads();            // done with As/Bs; reuse regX as Ys

    {
        float blv[8];
        #pragma unroll
        for (int oi = 0; oi < 8; oi++) blv[oi] = bl[c0 + oi];
        #pragma unroll
        for (int vi = 0; vi < 8; vi++)
            #pragma unroll
            for (int oi = 0; oi < 8; oi++)
                regX[(r0 + vi) * 68 + (c0 + oi)] = acc2[vi][oi] + blv[oi];
    }
    __syncthreads();

    // ================= Phase 6: layernorm, one voxel per thread =================
    if (active) {
        const float* y = regX + tid * 68;
        float s = 0.0f;
        #pragma unroll
        for (int c4 = 0; c4 < 16; c4++) {
            float4 f = *(const float4*)(y + 4 * c4);
            s += f.x + f.y + f.z + f.w;
        }
        float mu = s * (1.0f / 64.0f);
        float v2 = 0.0f;
        #pragma unroll
        for (int c4 = 0; c4 < 16; c4++) {
            float4 f = *(const float4*)(y + 4 * c4);
            float dx = f.x - mu, dy = f.y - mu, dz = f.z - mu, dw = f.w - mu;
            v2 += dx * dx + dy * dy + dz * dz + dw * dw;
        }
        float rstd = rsqrtf(v2 * (1.0f / 64.0f) + LN_EPS);
        float4* o4 = (float4*)(out + (long)gvox * COUT);
        #pragma unroll
        for (int c4 = 0; c4 < 16; c4++) {
            float4 f = *(const float4*)(y + 4 * c4);
            float4 g = *(const float4*)(gamma + 4 * c4);
            float4 b = *(const float4*)(beta + 4 * c4);
            float4 r;
            r.x = g.x * (f.x - mu) * rstd + b.x;
            r.y = g.y * (f.y - mu) * rstd + b.y;
            r.z = g.z * (f.z - mu) * rstd + b.z;
            r.w = g.w * (f.w - mu) * rstd + b.w;
            o4[c4] = r;
        }
    }
}

extern "C" void kernel_launch(void* const* d_in, const int* in_sizes, int n_in,
                              void* d_out, int out_size)
{
    const float* feats = (const float*)d_in[0];
    const int*   nb    = (const int*)d_in[1];
    const float* Wc    = (const float*)d_in[2];
    const float* bc    = (const float*)d_in[3];
    const float* Wl    = (const float*)d_in[4];
    const float* bl    = (const float*)d_in[5];
    const float* gamma = (const float*)d_in[6];
    const float* beta  = (const float*)d_in[7];
    float* out = (float*)d_out;

    static int smem_set = 0;
    if (!smem_set) {
        cudaFuncSetAttribute(spconv_lin_ln_kernel,
                             cudaFuncAttributeMaxDynamicSharedMemorySize, SMEM_BYTES);
        smem_set = 1;
    }

    int grid = (N_VOX + TILE_M - 1) / TILE_M;   // 782
    spconv_lin_ln_kernel<<<grid, NTHREADS, SMEM_BYTES>>>(feats, nb, Wc, bc, Wl, bl,
                                                         gamma, beta, out);
}